// round 16
// baseline (speedup 1.0000x reference)
#include <cuda_runtime.h>
#include <math.h>
#include <limits.h>

// WARP loss, R16: one 64-thread block per row; the block's TWO warps scan
// opposite halves of the row forward (R13's 2-buffer prefetch kept within
// each warp). Exactly one warp finds the positive and runs the tail; the
// other stops via a volatile smem flag ~1 round later. Max rounds/row 16->8,
// E 8.2->~4.6, register footprint identical to R13 (no spills).

#define FULL 0xFFFFFFFFu
#define BATCH1 16
#define CV 5                         // uint4 per lane per chunk -> 2.5KB
#define CHUNK (CV * 32)              // 160 vec per chunk

__device__ __forceinline__ void loadc(uint4 (&buf)[CV], const uint4* tv,
                                      int base, int lane, int hi) {
#pragma unroll
    for (int k = 0; k < CV; k++) {
        const int i = base + k * 32 + lane;
        buf[k] = (i < hi) ? __ldg(&tv[i]) : make_uint4(0u, 0u, 0u, 0u);
    }
}
// per-lane position of a nonzero in this chunk, or -1
__device__ __forceinline__ int testc(const uint4 (&buf)[CV], int base,
                                     int lane) {
    unsigned f = 0u;
#pragma unroll
    for (int k = 0; k < CV; k++)
        f |= (buf[k].x | buf[k].y | buf[k].z | buf[k].w);
    if (f == 0u) return -1;
    int p = -1;
#pragma unroll
    for (int k = 0; k < CV; k++) {
        const int i = base + k * 32 + lane;
        if (buf[k].x) p = 4 * i;
        if (buf[k].y) p = 4 * i + 1;
        if (buf[k].z) p = 4 * i + 2;
        if (buf[k].w) p = 4 * i + 3;
    }
    return p;
}

__global__ __launch_bounds__(64, 24)
void warp_loss_kernel(const float* __restrict__ input,
                      const float* __restrict__ target,
                      const int*   __restrict__ neg,
                      float* __restrict__ out,
                      int B, int T) {
    constexpr int Y    = 10000;
    constexpr int nvec = Y >> 2;                    // 2500 (Y % 4 == 0)
    constexpr int HALF = nvec / 2;                  // 1250 vec per warp
    constexpr int NCH  = (HALF + CHUNK - 1) / CHUNK;  // 8 chunks per half

    const int row  = blockIdx.x;
    const int wid  = threadIdx.x >> 5;              // 0: front half, 1: back
    const int lane = threadIdx.x & 31;

    __shared__ volatile int s_found;                // -1 until a warp finds
    if (threadIdx.x == 0) s_found = -1;

    const float* irow = input + (size_t)row * Y;
    const uint4* tv   = reinterpret_cast<const uint4*>(target + (size_t)row * Y);

    // --- eager gather of first BATCH1 trials (both warps; L2 dedups) ---
    int c_pre = 0;
    if (lane < BATCH1) c_pre = __ldg(&neg[(size_t)row * T + lane]);
    const float sc_pre = __ldg(&irow[c_pre]);       // lanes>=16: bcast irow[0]

    __syncthreads();                                // order s_found init

    const int lo = wid * HALF;                      // this warp's half
    const int hi = lo + HALF;

    // --- forward scan of own half, 2-buffer prefetch-1 (R13 structure) ---
    int pos = -1;
    {
        uint4 A[CV], Bb[CV];
        loadc(A, tv, lo, lane, hi);
#pragma unroll
        for (int c = 0; c < NCH; c += 2) {
            if (c + 1 < NCH) loadc(Bb, tv, lo + (c + 1) * CHUNK, lane, hi);
            int p = testc(A, lo + c * CHUNK, lane);
            if (__ballot_sync(FULL, p >= 0)) {
                pos = __reduce_min_sync(FULL, p >= 0 ? p : INT_MAX);
                break;
            }
            if (s_found >= 0) break;                // other warp resolved row
            if (c + 2 < NCH) loadc(A, tv, lo + (c + 2) * CHUNK, lane, hi);
            if (c + 1 < NCH) {
                p = testc(Bb, lo + (c + 1) * CHUNK, lane);
                if (__ballot_sync(FULL, p >= 0)) {
                    pos = __reduce_min_sync(FULL, p >= 0 ? p : INT_MAX);
                    break;
                }
            }
            if (s_found >= 0) break;
        }
    }

    if (pos < 0) return;          // non-finder warp: row owned by the other
    if (lane == 0) s_found = pos; // release the sibling warp ASAP

    const float sp = __ldg(&irow[pos]);             // broadcast load

    // --- first accepted among trials 0..15 (scores already in regs) ---
    const bool acc = (lane < BATCH1) && (1.0f + sc_pre - sp >= 0.0f);
    const unsigned m = __ballot_sync(FULL, acc);
    if (m) {
        const int first = __ffs(m) - 1;
        const float sn = __shfl_sync(FULL, sc_pre, first);
        if (lane == 0) {
            const int num_trials = first + 1;
            const float L = logf((float)((Y - 1) / num_trials));
            atomicAdd(out, L * (1.0f - sp + sn));
        }
    } else {
        // --- fallback (rare, ~0.3%): trials BATCH1..T-1, 32 at a time ---
        for (int t0 = BATCH1; t0 < T; t0 += 32) {
            const int t = t0 + lane;
            int c = 0;
            if (t < T) c = __ldg(&neg[(size_t)row * T + t]);
            const float sc = __ldg(&irow[c]);
            const bool a2 = (t < T) && (1.0f + sc - sp >= 0.0f);
            const unsigned m2 = __ballot_sync(FULL, a2);
            if (m2) {
                const int fl = __ffs(m2) - 1;
                const float sn = __shfl_sync(FULL, sc, fl);
                if (lane == 0) {
                    const int num_trials = t0 + fl + 1;
                    const float L = logf((float)((Y - 1) / num_trials));
                    atomicAdd(out, L * (1.0f - sp + sn));
                }
                break;
            }
        }
    }
}

extern "C" void kernel_launch(void* const* d_in, const int* in_sizes, int n_in,
                              void* d_out, int out_size) {
    const float* input  = (const float*)d_in[0];
    const float* target = (const float*)d_in[1];
    const int*   neg    = (const int*)d_in[2];
    float* out = (float*)d_out;

    const int Y = 10000;                 // fixed by problem spec
    const int B = in_sizes[0] / Y;       // 4096
    const int T = in_sizes[2] / B;       // 128

    cudaMemsetAsync(out, 0, (size_t)out_size * sizeof(float), 0);
    warp_loss_kernel<<<B, 64>>>(input, target, neg, out, B, T);
}

// round 17
// speedup vs baseline: 1.6430x; 1.6430x over previous
#include <cuda_runtime.h>
#include <math.h>
#include <limits.h>

// WARP loss, R17: R13 scan (warp-per-row, CV=5 two-buffer prefetch, lazy-16
// gather) + per-row loss written to a device scratch slot instead of 4096
// atomicAdds to one address (L2 atomic ALU serializes per-address ~0.854
// cyc/op -> ~2us bunched at wave end). A 1-block reduce kernel sums the
// 4096 slots into out[0]; it replaces the cudaMemsetAsync node.

#define FULL 0xFFFFFFFFu
#define BATCH1 16
#define CV 5                       // float4 per lane per chunk (2.5KB/chunk)
#define CHUNK (CV * 32)            // 160 float4 per chunk
#define MAX_B 4096

__device__ float g_loss[MAX_B];

__global__ __launch_bounds__(64, 16)
void warp_loss_kernel(const float* __restrict__ input,
                      const float* __restrict__ target,
                      const int*   __restrict__ neg,
                      int B, int T) {
    constexpr int Y    = 10000;
    constexpr int nvec = Y >> 2;                       // 2500 float4
    constexpr int NCH  = (nvec + CHUNK - 1) / CHUNK;   // 16 chunks

    const int gw   = blockIdx.x * 2 + (threadIdx.x >> 5);
    const int lane = threadIdx.x & 31;
    if (gw >= B) return;                               // warp-uniform

    const float* irow = input  + (size_t)gw * Y;
    const float* trow = target + (size_t)gw * Y;
    const float4* tv  = reinterpret_cast<const float4*>(trow);
    const float4 zero4 = make_float4(0.f, 0.f, 0.f, 0.f);

    // --- eager gather of first BATCH1 trials (independent of sp) ---
    int c_pre = 0;
    if (lane < BATCH1) c_pre = __ldg(&neg[(size_t)gw * T + lane]);
    const float sc_pre = __ldg(&irow[c_pre]);          // lanes>=16: bcast irow[0]

#define LOADC(buf, ch)                                              \
    {                                                               \
        _Pragma("unroll")                                           \
        for (int k = 0; k < CV; k++) {                              \
            const int _i = (ch) * CHUNK + k * 32 + lane;            \
            buf[k] = (_i < nvec) ? __ldg(&tv[_i]) : zero4;          \
        }                                                           \
    }
#define TESTC(buf, ch, pvar)                                        \
    {                                                               \
        _Pragma("unroll")                                           \
        for (int k = 0; k < CV; k++) {                              \
            const int _i = (ch) * CHUNK + k * 32 + lane;            \
            if (buf[k].x != 0.0f) pvar = 4 * _i;                    \
            if (buf[k].y != 0.0f) pvar = 4 * _i + 1;                \
            if (buf[k].z != 0.0f) pvar = 4 * _i + 2;                \
            if (buf[k].w != 0.0f) pvar = 4 * _i + 3;                \
        }                                                           \
    }

    // --- double-buffered scan: prefetch ch+1 while testing ch (R13) ---
    int pos = -1;
    {
        float4 A[CV], Bb[CV];
        LOADC(A, 0);
#pragma unroll
        for (int ch = 0; ch < NCH; ch += 2) {
            if (ch + 1 < NCH) LOADC(Bb, ch + 1);
            int p = -1;
            TESTC(A, ch, p);
            if (__ballot_sync(FULL, p >= 0)) {
                pos = __reduce_min_sync(FULL, p >= 0 ? p : INT_MAX);
                break;
            }
            if (ch + 2 < NCH) LOADC(A, ch + 2);
            p = -1;
            if (ch + 1 < NCH) TESTC(Bb, ch + 1, p);
            if (__ballot_sync(FULL, p >= 0)) {
                pos = __reduce_min_sync(FULL, p >= 0 ? p : INT_MAX);
                break;
            }
        }
    }
    if (pos < 0) pos = 0;                              // defensive (one-hot row)

    const float sp = __ldg(&irow[pos]);                // broadcast load

    // --- first accepted among trials 0..15 (scores already in regs) ---
    float loss = 0.0f;
    const bool acc = (lane < BATCH1) && (1.0f + sc_pre - sp >= 0.0f);
    const unsigned m = __ballot_sync(FULL, acc);
    if (m) {
        const int first = __ffs(m) - 1;
        const float sn = __shfl_sync(FULL, sc_pre, first);
        const int num_trials = first + 1;
        const float L = logf((float)((Y - 1) / num_trials));
        loss = L * (1.0f - sp + sn);
    } else {
        // --- fallback (rare, ~0.3%): trials BATCH1..T-1, 32 at a time ---
        for (int t0 = BATCH1; t0 < T; t0 += 32) {
            const int t = t0 + lane;
            int c = 0;
            if (t < T) c = __ldg(&neg[(size_t)gw * T + t]);
            const float sc = __ldg(&irow[c]);
            const bool a2 = (t < T) && (1.0f + sc - sp >= 0.0f);
            const unsigned m2 = __ballot_sync(FULL, a2);
            if (m2) {
                const int fl = __ffs(m2) - 1;
                const float sn = __shfl_sync(FULL, sc, fl);
                const int num_trials = t0 + fl + 1;
                const float L = logf((float)((Y - 1) / num_trials));
                loss = L * (1.0f - sp + sn);
                break;
            }
        }
    }
    if (lane == 0) g_loss[gw] = loss;   // every row writes -> no init needed
#undef LOADC
#undef TESTC
}

// Single-block tree reduction of g_loss[0..B) into out[0].
__global__ __launch_bounds__(256)
void reduce_kernel(float* __restrict__ out, int B) {
    __shared__ float s[8];
    const int tid = threadIdx.x;
    float acc = 0.0f;
    const float4* gl = reinterpret_cast<const float4*>(g_loss);
    for (int i = tid; i < (B >> 2); i += 256) {
        const float4 v = gl[i];
        acc += (v.x + v.y) + (v.z + v.w);
    }
    for (int i = (B & ~3) + tid; i < B; i += 256) acc += g_loss[i];
#pragma unroll
    for (int o = 16; o > 0; o >>= 1) acc += __shfl_down_sync(FULL, acc, o);
    if ((tid & 31) == 0) s[tid >> 5] = acc;
    __syncthreads();
    if (tid == 0) {
        float t = 0.0f;
#pragma unroll
        for (int k = 0; k < 8; k++) t += s[k];
        out[0] = t;
    }
}

extern "C" void kernel_launch(void* const* d_in, const int* in_sizes, int n_in,
                              void* d_out, int out_size) {
    const float* input  = (const float*)d_in[0];
    const float* target = (const float*)d_in[1];
    const int*   neg    = (const int*)d_in[2];
    float* out = (float*)d_out;

    const int Y = 10000;                 // fixed by problem spec
    const int B = in_sizes[0] / Y;       // 4096 (<= MAX_B)
    const int T = in_sizes[2] / B;       // 128

    warp_loss_kernel<<<(B + 1) / 2, 64>>>(input, target, neg, B, T);
    reduce_kernel<<<1, 256>>>(out, B);
}